// round 5
// baseline (speedup 1.0000x reference)
#include <cuda_runtime.h>
#include <cuda_bf16.h>

// Problem dims (fixed by the reference)
#define T_DIM 4
#define S_DIM 2048
#define D_DIM 768
#define SD (S_DIM * D_DIM)          // 1572864
#define TSD (T_DIM * SD)            // 6291456
#define N_HEADS 12
#define HEAD_DIM 64

typedef unsigned long long ull;

// Scratch (device globals: allocation-free)
__device__ float g_spk0[TSD];   // init spikes (0/1 as float)
__device__ float g_q[TSD];      // Q pre-BN, then Q spikes (in-place)
__device__ float g_k[TSD];      // K pre-BN, then K spikes (in-place)
__device__ float g_v[TSD];      // V pre-BN, then V spikes (in-place)
__device__ float g_o[TSD];      // final GEMM output pre-BN
__device__ float g_qk_raw[T_DIM * D_DIM];  // QK counts (exact integers)
__device__ float g_qk[T_DIM * D_DIM];      // talking-heads spikes (t, h*64+j)

__device__ __forceinline__ void fma2(ull &d, ull a, ull b) {
    asm("fma.rn.f32x2 %0, %1, %2, %0;" : "+l"(d) : "l"(a), "l"(b));
}

// ---------------------------------------------------------------------------
// K0: zero the QK accumulator (graph-safe, no memset API)
// ---------------------------------------------------------------------------
__global__ void k_zero_qk() {
    int i = blockIdx.x * blockDim.x + threadIdx.x;
    if (i < T_DIM * D_DIM) g_qk_raw[i] = 0.0f;
}

// ---------------------------------------------------------------------------
// K1: init_spike — IF node over T per (s,d). Exact elementwise fp32
// (bit-identical to the reference scan).
// ---------------------------------------------------------------------------
__global__ void k_init_spike(const float* __restrict__ x) {
    int idx = blockIdx.x * blockDim.x + threadIdx.x;
    if (idx >= SD) return;
    float v = 0.0f;
#pragma unroll
    for (int t = 0; t < T_DIM; t++) {
        v += x[t * SD + idx];
        float sp = (v >= 1.0f) ? 1.0f : 0.0f;
        g_spk0[t * SD + idx] = sp;
        if (sp != 0.0f) v = 0.0f;
    }
}

// ---------------------------------------------------------------------------
// GEMM: C(8192x768) = A(8192x768) @ B(768x768), fp32.
// Per-element accumulation: single accumulator, strictly ascending k, IEEE
// fma per step (fma.rn.f32x2 == two independent FFMAs) — the same chain a
// cuBLAS/Triton fp32 SIMT mainloop produces, maximizing bit-match odds.
// PHASE 0: A = g_spk0, three weights -> g_q / g_k / g_v (grid.x = 18)
// PHASE 1: A = g_v (V spikes) * g_qk mask (exact 0/1 product), B0=wo -> g_o
// Tile 128x128, BK=8, 256 threads, per-thread 8x8 via 32x fma.rn.f32x2.
// ---------------------------------------------------------------------------
template <int PHASE>
__global__ __launch_bounds__(256) void k_gemm(const float* __restrict__ B0,
                                              const float* __restrict__ B1,
                                              const float* __restrict__ B2) {
    __shared__ __align__(16) float2 As[8][128];  // A values duplicated (a,a)
    __shared__ __align__(16) float  Bs[8][128];

    const int tid = threadIdx.x;
    const float* A;
    const float* B;
    float* C;
    int col0;
    if (PHASE == 0) {
        int w = blockIdx.x / 6;
        col0 = (blockIdx.x % 6) * 128;
        A = g_spk0;
        B = (w == 0) ? B0 : ((w == 1) ? B1 : B2);
        C = (w == 0) ? g_q : ((w == 1) ? g_k : g_v);
    } else {
        col0 = blockIdx.x * 128;
        A = g_v;
        B = B0;
        C = g_o;
    }
    const int row0 = blockIdx.y * 128;

    // global-load mapping
    const int arow  = tid >> 1;          // 0..127
    const int akoff = (tid & 1) * 4;     // 0 or 4
    const int bk    = tid >> 5;          // 0..7
    const int bcol  = (tid & 31) * 4;    // 0..124

    // compute-fragment mapping (4 + 64-split for conflict-free LDS)
    const int ta4 = (tid >> 4) * 4;      // rows {ta4..+3, ta4+64..+67}
    const int tc4 = (tid & 15) * 4;      // cols {tc4..+3, tc4+64..+67}

    ull acc[8][4];
#pragma unroll
    for (int i = 0; i < 8; i++)
#pragma unroll
        for (int j = 0; j < 4; j++) acc[i][j] = 0ull;

    for (int k0 = 0; k0 < D_DIM; k0 += 8) {
        float4 av = *(const float4*)&A[(row0 + arow) * D_DIM + k0 + akoff];
        if (PHASE == 1) {
            // fuse QKV = V_spike * QK mask into the A load (exact 0/1 product)
            int t = (row0 + arow) >> 11;  // S_DIM = 2048 rows per t
            const float* q = &g_qk[t * D_DIM + k0 + akoff];
            av.x *= q[0]; av.y *= q[1]; av.z *= q[2]; av.w *= q[3];
        }
        float4 bv = *(const float4*)&B[(k0 + bk) * D_DIM + col0 + bcol];

        __syncthreads();
        As[akoff + 0][arow] = make_float2(av.x, av.x);
        As[akoff + 1][arow] = make_float2(av.y, av.y);
        As[akoff + 2][arow] = make_float2(av.z, av.z);
        As[akoff + 3][arow] = make_float2(av.w, av.w);
        *(float4*)&Bs[bk][bcol] = bv;
        __syncthreads();

#pragma unroll
        for (int kk = 0; kk < 8; kk++) {
            ull a[8], b[4];
            {
                ulonglong2 v0 = *(const ulonglong2*)&As[kk][ta4];
                ulonglong2 v1 = *(const ulonglong2*)&As[kk][ta4 + 2];
                ulonglong2 v2 = *(const ulonglong2*)&As[kk][ta4 + 64];
                ulonglong2 v3 = *(const ulonglong2*)&As[kk][ta4 + 66];
                a[0] = v0.x; a[1] = v0.y; a[2] = v1.x; a[3] = v1.y;
                a[4] = v2.x; a[5] = v2.y; a[6] = v3.x; a[7] = v3.y;
            }
            {
                ulonglong2 w0 = *(const ulonglong2*)&Bs[kk][tc4];
                ulonglong2 w1 = *(const ulonglong2*)&Bs[kk][tc4 + 64];
                b[0] = w0.x; b[1] = w0.y; b[2] = w1.x; b[3] = w1.y;
            }
#pragma unroll
            for (int i = 0; i < 8; i++)
#pragma unroll
                for (int j = 0; j < 4; j++) fma2(acc[i][j], a[i], b[j]);
        }
    }

#pragma unroll
    for (int i = 0; i < 8; i++) {
        int r = row0 + ((i < 4) ? (ta4 + i) : (ta4 + 64 + (i - 4)));
#pragma unroll
        for (int j = 0; j < 4; j++) {
            int c = col0 + ((j < 2) ? (tc4 + 2 * j) : (tc4 + 64 + 2 * (j - 2)));
            *(float2*)&C[r * D_DIM + c] = *(float2*)&acc[i][j];
        }
    }
}

// ---------------------------------------------------------------------------
// K3: BatchNorm1d over (T,D) per channel s, then IF node over T. In-place.
// Scalar math matches XLA: correctly-rounded div by 3072, libdevice rsqrtf.
// grid = (S_DIM, 3) -> tensor 0/1/2 = Q/K/V
// ---------------------------------------------------------------------------
__global__ void k_bn_if() {
    const int s = blockIdx.x;
    float* X = (blockIdx.y == 0) ? g_q : ((blockIdx.y == 1) ? g_k : g_v);
    __shared__ float sm[T_DIM * D_DIM];  // 12 KB
    __shared__ float red[256];
    const int tid = threadIdx.x;

    float psum = 0.0f;
    for (int i = tid; i < T_DIM * D_DIM; i += 256) {
        int t = i / D_DIM, d = i - t * D_DIM;
        float val = X[t * SD + s * D_DIM + d];
        sm[i] = val;
        psum += val;
    }
    red[tid] = psum;
    __syncthreads();
    for (int off = 128; off; off >>= 1) {
        if (tid < off) red[tid] += red[tid + off];
        __syncthreads();
    }
    float mean = red[0] / 3072.0f;
    __syncthreads();

    float pv = 0.0f;
    for (int i = tid; i < T_DIM * D_DIM; i += 256) {
        float dv = sm[i] - mean;
        pv += dv * dv;
    }
    red[tid] = pv;
    __syncthreads();
    for (int off = 128; off; off >>= 1) {
        if (tid < off) red[tid] += red[tid + off];
        __syncthreads();
    }
    float var = red[0] / 3072.0f;
    float rs = rsqrtf(var + 1e-5f);

    for (int d = tid; d < D_DIM; d += 256) {
        float v = 0.0f;
#pragma unroll
        for (int t = 0; t < T_DIM; t++) {
            float val = (sm[t * D_DIM + d] - mean) * rs;
            v += val;
            float sp = (v >= 1.0f) ? 1.0f : 0.0f;
            X[t * SD + s * D_DIM + d] = sp;
            if (sp != 0.0f) v = 0.0f;
        }
    }
}

// ---------------------------------------------------------------------------
// K4a: QK counts — coalesced partial sums + float atomics. All partials are
// integers (binary products), so the result is EXACT and order-independent
// (fp32 adds of integers < 2^24 are exact) -> deterministic despite atomics.
// grid = (T_DIM * 3 [c-chunks of 256], 8 [s-chunks of 256]), 256 threads.
// ---------------------------------------------------------------------------
__global__ void k_qk_partial() {
    const int t = blockIdx.x / 3;
    const int c = (blockIdx.x % 3) * 256 + threadIdx.x;
    const int s0 = blockIdx.y * 256;
    const float* Qp = &g_q[t * SD + s0 * D_DIM + c];
    const float* Kp = &g_k[t * SD + s0 * D_DIM + c];
    float acc = 0.0f;
#pragma unroll 8
    for (int s = 0; s < 256; s++)
        acc += Qp[s * D_DIM] * Kp[s * D_DIM];
    atomicAdd(&g_qk_raw[t * D_DIM + c], acc);
}

// K4b: IF node over T on the exact integer counts -> talking-heads spikes.
__global__ void k_qk_fin() {
    int c = blockIdx.x * blockDim.x + threadIdx.x;
    if (c >= D_DIM) return;
    float v = 0.0f;
#pragma unroll
    for (int t = 0; t < T_DIM; t++) {
        v += g_qk_raw[t * D_DIM + c];
        float sp = (v >= 1.0f) ? 1.0f : 0.0f;
        g_qk[t * D_DIM + c] = sp;
        if (sp != 0.0f) v = 0.0f;
    }
}

// ---------------------------------------------------------------------------
// K7: final BatchNorm1d over (T,D) per channel s -> d_out.
// ---------------------------------------------------------------------------
__global__ void k_bn_out(float* __restrict__ out) {
    const int s = blockIdx.x;
    __shared__ float sm[T_DIM * D_DIM];
    __shared__ float red[256];
    const int tid = threadIdx.x;

    float psum = 0.0f;
    for (int i = tid; i < T_DIM * D_DIM; i += 256) {
        int t = i / D_DIM, d = i - t * D_DIM;
        float val = g_o[t * SD + s * D_DIM + d];
        sm[i] = val;
        psum += val;
    }
    red[tid] = psum;
    __syncthreads();
    for (int off = 128; off; off >>= 1) {
        if (tid < off) red[tid] += red[tid + off];
        __syncthreads();
    }
    float mean = red[0] / 3072.0f;
    __syncthreads();

    float pv = 0.0f;
    for (int i = tid; i < T_DIM * D_DIM; i += 256) {
        float dv = sm[i] - mean;
        pv += dv * dv;
    }
    red[tid] = pv;
    __syncthreads();
    for (int off = 128; off; off >>= 1) {
        if (tid < off) red[tid] += red[tid + off];
        __syncthreads();
    }
    float var = red[0] / 3072.0f;
    float rs = rsqrtf(var + 1e-5f);

    for (int i = tid; i < T_DIM * D_DIM; i += 256) {
        int t = i / D_DIM, d = i - t * D_DIM;
        out[t * SD + s * D_DIM + d] = (sm[i] - mean) * rs;
    }
}

// ---------------------------------------------------------------------------
// Launch: graph-capturable, allocation-free, deterministic.
// Inputs (metadata order): x, wq, wk, wv, wo, cur_pos(unused)
// ---------------------------------------------------------------------------
extern "C" void kernel_launch(void* const* d_in, const int* in_sizes, int n_in,
                              void* d_out, int out_size) {
    const float* x  = (const float*)d_in[0];
    const float* wq = (const float*)d_in[1];
    const float* wk = (const float*)d_in[2];
    const float* wv = (const float*)d_in[3];
    const float* wo = (const float*)d_in[4];
    float* out = (float*)d_out;

    // 0. zero QK accumulator (independent; launched first)
    k_zero_qk<<<(T_DIM * D_DIM + 255) / 256, 256>>>();

    // 1. init spikes
    k_init_spike<<<(SD + 255) / 256, 256>>>(x);

    // 2. Q/K/V projections (one fused GEMM launch, 3 weights)
    {
        dim3 grid(18, 64);
        k_gemm<0><<<grid, 256>>>(wq, wk, wv);
    }

    // 3. BN + IF for Q, K, V (in-place -> spikes)
    {
        dim3 grid(S_DIM, 3);
        k_bn_if<<<grid, 256>>>();
    }

    // 4. talking-heads QK reduction + IF
    {
        dim3 grid(T_DIM * 3, 8);
        k_qk_partial<<<grid, 256>>>();
        k_qk_fin<<<(D_DIM + 255) / 256, 256>>>();
    }

    // 5. final GEMM: (V_spike * QK) @ wo  (mask fused into A load)
    {
        dim3 grid(6, 64);
        k_gemm<1><<<grid, 256>>>(wo, wo, wo);
    }

    // 6. final BN -> output
    k_bn_out<<<S_DIM, 256>>>(out);
}